// round 6
// baseline (speedup 1.0000x reference)
#include <cuda_runtime.h>
#include <cuda_fp16.h>
#include <cstdint>

// ---------------------------------------------------------------------------
// Problem constants
// ---------------------------------------------------------------------------
#define D_MODEL 512
#define NHEAD   8
#define DK      64
#define BATCH   8192
#define SEQ     14
#define MROWS   (BATCH*SEQ)   // 114688

// Scratch (static device globals)
__device__ __half g_Xh  [(size_t)MROWS * D_MODEL];  // X in fp16
__device__ __half g_QKVh[(size_t)MROWS * 1536];     // Q|K|V fused, fp16
__device__ __half g_attnh[(size_t)MROWS * D_MODEL]; // attention out, fp16
__device__ __half g_Wh  [2048 * 512];               // Wq;Wk;Wv;Wo fp16 (row-major over k)
__device__ float  g_bias[2048];                     // bq;bk;bv;bo

// ---------------------------------------------------------------------------
// Helpers
// ---------------------------------------------------------------------------
__device__ __forceinline__ uint32_t smem_u32(const void* p) {
    uint32_t a;
    asm("{ .reg .u64 t; cvta.to.shared.u64 t, %1; cvt.u32.u64 %0, t; }" : "=r"(a) : "l"(p));
    return a;
}
__device__ __forceinline__ void cp16(uint32_t dst, const void* src) {
    asm volatile("cp.async.cg.shared.global [%0], [%1], 16;\n" :: "r"(dst), "l"(src));
}
__device__ __forceinline__ void cp_commit() { asm volatile("cp.async.commit_group;\n" ::: "memory"); }
template <int N> __device__ __forceinline__ void cp_wait() {
    asm volatile("cp.async.wait_group %0;\n" :: "n"(N) : "memory");
}
__device__ __forceinline__ void ldsm_x4(uint32_t r[4], uint32_t addr) {
    asm volatile("ldmatrix.sync.aligned.m8n8.x4.shared.b16 {%0,%1,%2,%3}, [%4];"
                 : "=r"(r[0]), "=r"(r[1]), "=r"(r[2]), "=r"(r[3]) : "r"(addr));
}
__device__ __forceinline__ void mma16816(float c[4], const uint32_t a[4], const uint32_t b[2]) {
    asm volatile(
        "mma.sync.aligned.m16n8k16.row.col.f32.f16.f16.f32 "
        "{%0,%1,%2,%3}, {%4,%5,%6,%7}, {%8,%9}, {%0,%1,%2,%3};\n"
        : "+f"(c[0]), "+f"(c[1]), "+f"(c[2]), "+f"(c[3])
        : "r"(a[0]), "r"(a[1]), "r"(a[2]), "r"(a[3]), "r"(b[0]), "r"(b[1]));
}

// ---------------------------------------------------------------------------
// fp16 multistage GEMM (unchanged from R5): CTA 128x128, BK=32, 4-stage
// cp.async pipeline, 4 warps (warp tile 64x64), ldmatrix fragments.
// ---------------------------------------------------------------------------
#define BM 128
#define BN 128
#define BK 32
#define NSTAGE 4
#define NK (D_MODEL / BK)               // 16
#define ROW_B 80                        // 64B data + 16B pad (conflict-free ldmatrix)
#define A_ST  (BM * ROW_B)              // 10240
#define B_ST  (BN * ROW_B)              // 10240
#define STAGE (A_ST + B_ST)             // 20480
#define SM_BIAS (NSTAGE * STAGE)        // 81920
#define SM_TOTAL (SM_BIAS + BN * 4)     // 82432
#define GTHREADS 128

__device__ __forceinline__ void issue_stage(uint32_t sb, int buf, int ks,
                                            const __half* __restrict__ Abase,
                                            const __half* __restrict__ Wbase,
                                            int tid) {
    const uint32_t adst = sb + buf * STAGE;
    const uint32_t bdst = adst + A_ST;
    const int kb = ks * BK;
    #pragma unroll
    for (int t = 0; t < 4; t++) {
        int c = tid + t * GTHREADS;      // 0..511
        int r = c >> 2, kc = c & 3;      // row 0..127, 16B chunk 0..3
        cp16(adst + (uint32_t)(r * ROW_B + kc * 16), Abase + (long)r * D_MODEL + kb + kc * 8);
    }
    #pragma unroll
    for (int t = 0; t < 4; t++) {
        int c = tid + t * GTHREADS;
        int r = c >> 2, kc = c & 3;
        cp16(bdst + (uint32_t)(r * ROW_B + kc * 16), Wbase + (long)r * D_MODEL + kb + kc * 8);
    }
}

template <typename OutT>
__global__ __launch_bounds__(GTHREADS, 2)
void gemm_fp16(const __half* __restrict__ A, const __half* __restrict__ W,
               const float* __restrict__ bias, OutT* __restrict__ out,
               int ldo, int wbase)
{
    extern __shared__ char smem[];
    const uint32_t sb = smem_u32(smem);
    float* sBias = (float*)(smem + SM_BIAS);

    const int tid = threadIdx.x;
    const int wid = tid >> 5, lane = tid & 31;
    const int wm = wid >> 1, wn = wid & 1;       // warp tile: rows wm*64, cols wn*64
    const int bx = blockIdx.x, by = blockIdx.y;
    const long row0  = (long)by * BM;
    const int  wrow0 = wbase + bx * BN;

    if (tid < BN) sBias[tid] = bias[wrow0 + tid];

    const __half* Abase = A + row0 * D_MODEL;
    const __half* Wbase = W + (long)wrow0 * D_MODEL;

    float acc[4][8][4];
    #pragma unroll
    for (int i = 0; i < 4; i++)
        #pragma unroll
        for (int j = 0; j < 8; j++)
            #pragma unroll
            for (int k = 0; k < 4; k++) acc[i][j][k] = 0.f;

    const int sub = lane >> 3, l7 = lane & 7;
    const uint32_t a_off = (uint32_t)((wm * 64 + (sub & 1) * 8 + l7) * ROW_B + (sub >> 1) * 16);
    const uint32_t b_off = (uint32_t)((wn * 64 + (sub >> 1) * 8 + l7) * ROW_B + (sub & 1) * 16);

    #pragma unroll
    for (int s = 0; s < NSTAGE - 1; s++) { issue_stage(sb, s, s, Abase, Wbase, tid); cp_commit(); }

    for (int ks = 0; ks < NK; ks++) {
        const int buf = ks & (NSTAGE - 1);
        cp_wait<NSTAGE - 2>();
        __syncthreads();

        const int pf = ks + NSTAGE - 1;
        if (pf < NK) issue_stage(sb, pf & (NSTAGE - 1), pf, Abase, Wbase, tid);
        cp_commit();

        const uint32_t abase = sb + buf * STAGE;
        const uint32_t bbase = abase + A_ST;
        #pragma unroll
        for (int slab = 0; slab < 2; slab++) {      // two k16 slabs per stage
            const uint32_t koff = (uint32_t)(slab * 32);
            uint32_t afr[4][4], bfr[8][2];
            #pragma unroll
            for (int mt = 0; mt < 4; mt++)
                ldsm_x4(afr[mt], abase + a_off + (uint32_t)(mt * 16 * ROW_B) + koff);
            #pragma unroll
            for (int ntp = 0; ntp < 4; ntp++) {
                uint32_t r4[4];
                ldsm_x4(r4, bbase + b_off + (uint32_t)(ntp * 16 * ROW_B) + koff);
                bfr[2 * ntp][0] = r4[0]; bfr[2 * ntp][1] = r4[1];
                bfr[2 * ntp + 1][0] = r4[2]; bfr[2 * ntp + 1][1] = r4[3];
            }
            #pragma unroll
            for (int mt = 0; mt < 4; mt++)
                #pragma unroll
                for (int nt = 0; nt < 8; nt++)
                    mma16816(acc[mt][nt], afr[mt], bfr[nt]);
        }
    }

    const int rl = lane >> 2, cl = 2 * (lane & 3);
    #pragma unroll
    for (int mt = 0; mt < 4; mt++) {
        const long r = row0 + wm * 64 + mt * 16 + rl;
        #pragma unroll
        for (int nt = 0; nt < 8; nt++) {
            const int c = wn * 64 + nt * 8 + cl;
            const long cg = (long)bx * BN + c;
            const float b0 = sBias[c], b1 = sBias[c + 1];
            if constexpr (sizeof(OutT) == 2) {
                __half2* p0 = (__half2*)((__half*)out + r * ldo + cg);
                __half2* p1 = (__half2*)((__half*)out + (r + 8) * ldo + cg);
                *p0 = __float22half2_rn(make_float2(acc[mt][nt][0] + b0, acc[mt][nt][1] + b1));
                *p1 = __float22half2_rn(make_float2(acc[mt][nt][2] + b0, acc[mt][nt][3] + b1));
            } else {
                float* o = (float*)out;
                *(float2*)&o[r * ldo + cg] =
                    make_float2(acc[mt][nt][0] + b0, acc[mt][nt][1] + b1);
                *(float2*)&o[(r + 8) * ldo + cg] =
                    make_float2(acc[mt][nt][2] + b0, acc[mt][nt][3] + b1);
            }
        }
    }
}

// ---------------------------------------------------------------------------
// Attention v5 — 512 threads/block, 2 warps per head, f32 smem (convert ONCE
// during staging; hot loops are pure LDS.128 + FFMA, zero cvts).
// Lane = (g, n): g = (warp&1)*2 + (lane>>4) selects 16 dims [g*16, g*16+16),
// n = lane&15 = query row (active n<14).
// ---------------------------------------------------------------------------
#define AQ_F        (SEQ * 1536)                        // 21504 floats
#define SPART_OFF   (AQ_F * 4)                          // 86016 B
#define SPART_SZ    (NHEAD * 2 * 16 * 17 * 4)           // 17408 B
#define SPRIOR_OFF  (SPART_OFF + SPART_SZ)              // 103424 B
#define ATTN_SMEM   (SPRIOR_OFF + SEQ * SEQ * 4)        // 104208 B

__global__ __launch_bounds__(512, 2)
void attn_kernel(const float* __restrict__ dist,
                 const float* __restrict__ scaleP,
                 const float* __restrict__ powerP)
{
    extern __shared__ char asm_[];
    float* sQKV   = (float*)asm_;                       // [SEQ][1536] f32
    float* sPart  = (float*)(asm_ + SPART_OFF);         // [8][2][16][17]
    float* sPrior = (float*)(asm_ + SPRIOR_OFF);        // [SEQ*SEQ]

    const int tid = threadIdx.x, lane = tid & 31, wid = tid >> 5;
    const int h = wid >> 1, w = wid & 1;
    const int b = blockIdx.x;

    if (tid < SEQ * SEQ) {
        float d  = dist[tid];
        float p  = powerP[0];
        float sc = scaleP[0];
        float dp = (d > 0.f) ? expf(p * logf(d)) : 0.f;
        sPrior[tid] = sc / (1.f + dp) * 0.125f;         // fold in 1/sqrt(64)
    }

    // Stage QKV (half -> f32 ONCE): 2688 uint4 chunks, coalesced
    {
        const uint4* src = (const uint4*)(g_QKVh + (size_t)b * AQ_F);
        for (int i = tid; i < AQ_F / 8; i += 512) {
            uint4 v = src[i];
            float2 f0 = __half22float2(*(__half2*)&v.x);
            float2 f1 = __half22float2(*(__half2*)&v.y);
            float2 f2 = __half22float2(*(__half2*)&v.z);
            float2 f3 = __half22float2(*(__half2*)&v.w);
            *(float4*)&sQKV[i * 8]     = make_float4(f0.x, f0.y, f1.x, f1.y);
            *(float4*)&sQKV[i * 8 + 4] = make_float4(f2.x, f2.y, f3.x, f3.y);
        }
    }
    __syncthreads();

    const int gq = w * 2 + (lane >> 4);   // dim quarter 0..3
    const int n  = lane & 15;             // query row (valid < SEQ)
    const int ne = (n < SEQ) ? n : SEQ - 1;
    const int cb = h * DK + gq * 16;      // column base within 512 (floats)

    // Q segment (16 dims) -> regs
    float q[16];
    {
        const float* qp = sQKV + ne * 1536 + cb;
        #pragma unroll
        for (int j = 0; j < 4; j++) {
            float4 v = *(const float4*)(qp + 4 * j);
            q[4 * j] = v.x; q[4 * j + 1] = v.y; q[4 * j + 2] = v.z; q[4 * j + 3] = v.w;
        }
    }

    // Partial scores over this lane's 16 dims (K row loads are warp-broadcast)
    float sc[SEQ];
    #pragma unroll
    for (int m = 0; m < SEQ; m++) {
        const float* kp = sQKV + m * 1536 + 512 + cb;
        float a = 0.f;
        #pragma unroll
        for (int j = 0; j < 4; j++) {
            float4 v = *(const float4*)(kp + 4 * j);
            a += q[4 * j] * v.x + q[4 * j + 1] * v.y
               + q[4 * j + 2] * v.z + q[4 * j + 3] * v.w;
        }
        sc[m] = a;
    }
    // Combine the warp's two 16-dim quarters -> 32-dim partial
    #pragma unroll
    for (int m = 0; m < SEQ; m++)
        sc[m] += __shfl_xor_sync(0xffffffffu, sc[m], 16);

    // Cross-warp exchange: warp w holds dims [w*32, w*32+32)
    float* myPart = sPart + ((h * 2 + w) * 16 + n) * 17;
    if (lane < 16) {
        #pragma unroll
        for (int m = 0; m < SEQ; m++) myPart[m] = sc[m];
    }
    __syncthreads();

    {
        const float* p0 = sPart + ((h * 2 + 0) * 16 + n) * 17;
        const float* p1 = sPart + ((h * 2 + 1) * 16 + n) * 17;
        const float* pr = sPrior + ne * SEQ;
        #pragma unroll
        for (int m = 0; m < SEQ; m++)
            sc[m] = (p0[m] + p1[m]) * pr[m];
    }

    // Lane-local softmax
    float mx = sc[0];
    #pragma unroll
    for (int m = 1; m < SEQ; m++) mx = fmaxf(mx, sc[m]);
    float sum = 0.f;
    #pragma unroll
    for (int m = 0; m < SEQ; m++) { sc[m] = __expf(sc[m] - mx); sum += sc[m]; }
    const float inv = 1.f / sum;

    // Out = attn @ V for this lane's 16 dims (V row loads are warp-broadcast)
    float acc[16];
    #pragma unroll
    for (int d = 0; d < 16; d++) acc[d] = 0.f;
    #pragma unroll
    for (int m = 0; m < SEQ; m++) {
        const float wgt = sc[m] * inv;
        const float* vp = sQKV + m * 1536 + 1024 + cb;
        #pragma unroll
        for (int j = 0; j < 4; j++) {
            float4 v = *(const float4*)(vp + 4 * j);
            acc[4 * j]     += wgt * v.x;
            acc[4 * j + 1] += wgt * v.y;
            acc[4 * j + 2] += wgt * v.z;
            acc[4 * j + 3] += wgt * v.w;
        }
    }

    // Store 16 halves (feeds fp16 GEMM2)
    if (n < SEQ) {
        __half* outp = g_attnh + (size_t)b * (SEQ * 512) + n * 512 + cb;
        uint4 v0, v1;
        __half2* o0 = (__half2*)&v0;
        __half2* o1 = (__half2*)&v1;
        #pragma unroll
        for (int j = 0; j < 4; j++) {
            o0[j] = __float22half2_rn(make_float2(acc[2 * j], acc[2 * j + 1]));
            o1[j] = __float22half2_rn(make_float2(acc[8 + 2 * j], acc[8 + 2 * j + 1]));
        }
        ((uint4*)outp)[0] = v0;
        ((uint4*)outp)[1] = v1;
    }
}

// ---------------------------------------------------------------------------
// Conversions
// ---------------------------------------------------------------------------
__global__ void conv_x_kernel(const float* __restrict__ x, __half* __restrict__ o, long n4) {
    long i = (long)blockIdx.x * blockDim.x + threadIdx.x;
    const long stride = (long)gridDim.x * blockDim.x;
    const float4* xi = (const float4*)x;
    for (; i < n4; i += stride) {
        float4 v = xi[i];
        __half2 lo = __float22half2_rn(make_float2(v.x, v.y));
        __half2 hi = __float22half2_rn(make_float2(v.z, v.w));
        *(uint2*)(o + i * 4) = make_uint2(*(uint32_t*)&lo, *(uint32_t*)&hi);
    }
}

__global__ void conv_w_kernel(const float* __restrict__ Wq, const float* __restrict__ Wk,
                              const float* __restrict__ Wv, const float* __restrict__ Wo,
                              const float* __restrict__ bq, const float* __restrict__ bk,
                              const float* __restrict__ bv, const float* __restrict__ bo,
                              __half* __restrict__ Wc, float* __restrict__ bias) {
    int i = blockIdx.x * 256 + threadIdx.x;
    if (i < 2048 * 512) {
        int r = i >> 9, c = i & 511;
        const float* src = (r < 512) ? Wq : (r < 1024) ? Wk : (r < 1536) ? Wv : Wo;
        Wc[i] = __float2half_rn(src[(r & 511) * 512 + c]);
    }
    if (i < 2048) {
        const float* bs = (i < 512) ? bq : (i < 1024) ? bk : (i < 1536) ? bv : bo;
        bias[i] = bs[i & 511];
    }
}

// ---------------------------------------------------------------------------
// Launch
// ---------------------------------------------------------------------------
extern "C" void kernel_launch(void* const* d_in, const int* in_sizes, int n_in,
                              void* d_out, int out_size)
{
    const float* x     = (const float*)d_in[0];
    const float* Wq    = (const float*)d_in[1];
    const float* bq    = (const float*)d_in[2];
    const float* Wk    = (const float*)d_in[3];
    const float* bk    = (const float*)d_in[4];
    const float* Wv    = (const float*)d_in[5];
    const float* bv    = (const float*)d_in[6];
    const float* Wo    = (const float*)d_in[7];
    const float* bo    = (const float*)d_in[8];
    const float* scale = (const float*)d_in[9];
    const float* power = (const float*)d_in[10];
    const float* dist  = (const float*)d_in[11];
    float* out = (float*)d_out;

    __half *Xh = nullptr, *qkvh = nullptr, *attnh = nullptr, *Wh = nullptr;
    float *bias = nullptr;
    cudaGetSymbolAddress((void**)&Xh,    g_Xh);
    cudaGetSymbolAddress((void**)&qkvh,  g_QKVh);
    cudaGetSymbolAddress((void**)&attnh, g_attnh);
    cudaGetSymbolAddress((void**)&Wh,    g_Wh);
    cudaGetSymbolAddress((void**)&bias,  g_bias);

    cudaFuncSetAttribute(gemm_fp16<__half>, cudaFuncAttributeMaxDynamicSharedMemorySize, SM_TOTAL);
    cudaFuncSetAttribute(gemm_fp16<float>,  cudaFuncAttributeMaxDynamicSharedMemorySize, SM_TOTAL);
    cudaFuncSetAttribute(attn_kernel, cudaFuncAttributeMaxDynamicSharedMemorySize, ATTN_SMEM);

    conv_x_kernel<<<4096, 256>>>(x, Xh, (long)MROWS * D_MODEL / 4);
    conv_w_kernel<<<4096, 256>>>(Wq, Wk, Wv, Wo, bq, bk, bv, bo, Wh, bias);

    // QKV projection -> g_QKVh [M x 1536] (half)
    gemm_fp16<__half><<<dim3(12, MROWS / BM), GTHREADS, SM_TOTAL>>>(Xh, Wh, bias, qkvh, 1536, 0);

    // Attention per batch item -> g_attnh (half)
    attn_kernel<<<BATCH, 512, ATTN_SMEM>>>(dist, scale, power);

    // Output projection -> d_out [M x 512] (f32)
    gemm_fp16<float><<<dim3(4, MROWS / BM), GTHREADS, SM_TOTAL>>>(attnh, Wh, bias, out, 512, 1536);
}

// round 7
// speedup vs baseline: 1.1665x; 1.1665x over previous
#include <cuda_runtime.h>
#include <cuda_fp16.h>
#include <cstdint>

// ---------------------------------------------------------------------------
// Problem constants
// ---------------------------------------------------------------------------
#define D_MODEL 512
#define NHEAD   8
#define DK      64
#define BATCH   8192
#define SEQ     14
#define MROWS   (BATCH*SEQ)   // 114688

// Scratch (static device globals)
__device__ __half g_Xh  [(size_t)MROWS * D_MODEL];  // X in fp16
__device__ __half g_QKVh[(size_t)MROWS * 1536];     // Q|K|V fused, fp16
__device__ __half g_attnh[(size_t)MROWS * D_MODEL]; // attention out, fp16
__device__ __half g_Wh  [2048 * 512];               // Wq;Wk;Wv;Wo fp16 (row-major over k)
__device__ float  g_bias[2048];                     // bq;bk;bv;bo

// ---------------------------------------------------------------------------
// Helpers
// ---------------------------------------------------------------------------
__device__ __forceinline__ uint32_t smem_u32(const void* p) {
    uint32_t a;
    asm("{ .reg .u64 t; cvta.to.shared.u64 t, %1; cvt.u32.u64 %0, t; }" : "=r"(a) : "l"(p));
    return a;
}
__device__ __forceinline__ void cp16(uint32_t dst, const void* src) {
    asm volatile("cp.async.cg.shared.global [%0], [%1], 16;\n" :: "r"(dst), "l"(src));
}
__device__ __forceinline__ void cp_commit() { asm volatile("cp.async.commit_group;\n" ::: "memory"); }
template <int N> __device__ __forceinline__ void cp_wait() {
    asm volatile("cp.async.wait_group %0;\n" :: "n"(N) : "memory");
}
__device__ __forceinline__ void ldsm_x4(uint32_t r[4], uint32_t addr) {
    asm volatile("ldmatrix.sync.aligned.m8n8.x4.shared.b16 {%0,%1,%2,%3}, [%4];"
                 : "=r"(r[0]), "=r"(r[1]), "=r"(r[2]), "=r"(r[3]) : "r"(addr));
}
__device__ __forceinline__ void ldsm_x4_t(uint32_t r[4], uint32_t addr) {
    asm volatile("ldmatrix.sync.aligned.m8n8.x4.trans.shared.b16 {%0,%1,%2,%3}, [%4];"
                 : "=r"(r[0]), "=r"(r[1]), "=r"(r[2]), "=r"(r[3]) : "r"(addr));
}
__device__ __forceinline__ void mma16816(float c[4], const uint32_t a[4], const uint32_t b[2]) {
    asm volatile(
        "mma.sync.aligned.m16n8k16.row.col.f32.f16.f16.f32 "
        "{%0,%1,%2,%3}, {%4,%5,%6,%7}, {%8,%9}, {%0,%1,%2,%3};\n"
        : "+f"(c[0]), "+f"(c[1]), "+f"(c[2]), "+f"(c[3])
        : "r"(a[0]), "r"(a[1]), "r"(a[2]), "r"(a[3]), "r"(b[0]), "r"(b[1]));
}

// ---------------------------------------------------------------------------
// fp16 multistage GEMM (unchanged from R5 best): CTA 128x128, BK=32, 4-stage
// cp.async pipeline, 4 warps (warp tile 64x64), ldmatrix fragments.
// ---------------------------------------------------------------------------
#define BM 128
#define BN 128
#define BK 32
#define NSTAGE 4
#define NK (D_MODEL / BK)               // 16
#define ROW_B 80                        // 64B data + 16B pad (conflict-free ldmatrix)
#define A_ST  (BM * ROW_B)              // 10240
#define B_ST  (BN * ROW_B)              // 10240
#define STAGE (A_ST + B_ST)             // 20480
#define SM_BIAS (NSTAGE * STAGE)        // 81920
#define SM_TOTAL (SM_BIAS + BN * 4)     // 82432
#define GTHREADS 128

__device__ __forceinline__ void issue_stage(uint32_t sb, int buf, int ks,
                                            const __half* __restrict__ Abase,
                                            const __half* __restrict__ Wbase,
                                            int tid) {
    const uint32_t adst = sb + buf * STAGE;
    const uint32_t bdst = adst + A_ST;
    const int kb = ks * BK;
    #pragma unroll
    for (int t = 0; t < 4; t++) {
        int c = tid + t * GTHREADS;      // 0..511
        int r = c >> 2, kc = c & 3;      // row 0..127, 16B chunk 0..3
        cp16(adst + (uint32_t)(r * ROW_B + kc * 16), Abase + (long)r * D_MODEL + kb + kc * 8);
    }
    #pragma unroll
    for (int t = 0; t < 4; t++) {
        int c = tid + t * GTHREADS;
        int r = c >> 2, kc = c & 3;
        cp16(bdst + (uint32_t)(r * ROW_B + kc * 16), Wbase + (long)r * D_MODEL + kb + kc * 8);
    }
}

template <typename OutT>
__global__ __launch_bounds__(GTHREADS, 2)
void gemm_fp16(const __half* __restrict__ A, const __half* __restrict__ W,
               const float* __restrict__ bias, OutT* __restrict__ out,
               int ldo, int wbase)
{
    extern __shared__ char smem[];
    const uint32_t sb = smem_u32(smem);
    float* sBias = (float*)(smem + SM_BIAS);

    const int tid = threadIdx.x;
    const int wid = tid >> 5, lane = tid & 31;
    const int wm = wid >> 1, wn = wid & 1;       // warp tile: rows wm*64, cols wn*64
    const int bx = blockIdx.x, by = blockIdx.y;
    const long row0  = (long)by * BM;
    const int  wrow0 = wbase + bx * BN;

    if (tid < BN) sBias[tid] = bias[wrow0 + tid];

    const __half* Abase = A + row0 * D_MODEL;
    const __half* Wbase = W + (long)wrow0 * D_MODEL;

    float acc[4][8][4];
    #pragma unroll
    for (int i = 0; i < 4; i++)
        #pragma unroll
        for (int j = 0; j < 8; j++)
            #pragma unroll
            for (int k = 0; k < 4; k++) acc[i][j][k] = 0.f;

    const int sub = lane >> 3, l7 = lane & 7;
    const uint32_t a_off = (uint32_t)((wm * 64 + (sub & 1) * 8 + l7) * ROW_B + (sub >> 1) * 16);
    const uint32_t b_off = (uint32_t)((wn * 64 + (sub >> 1) * 8 + l7) * ROW_B + (sub & 1) * 16);

    #pragma unroll
    for (int s = 0; s < NSTAGE - 1; s++) { issue_stage(sb, s, s, Abase, Wbase, tid); cp_commit(); }

    for (int ks = 0; ks < NK; ks++) {
        const int buf = ks & (NSTAGE - 1);
        cp_wait<NSTAGE - 2>();
        __syncthreads();

        const int pf = ks + NSTAGE - 1;
        if (pf < NK) issue_stage(sb, pf & (NSTAGE - 1), pf, Abase, Wbase, tid);
        cp_commit();

        const uint32_t abase = sb + buf * STAGE;
        const uint32_t bbase = abase + A_ST;
        #pragma unroll
        for (int slab = 0; slab < 2; slab++) {      // two k16 slabs per stage
            const uint32_t koff = (uint32_t)(slab * 32);
            uint32_t afr[4][4], bfr[8][2];
            #pragma unroll
            for (int mt = 0; mt < 4; mt++)
                ldsm_x4(afr[mt], abase + a_off + (uint32_t)(mt * 16 * ROW_B) + koff);
            #pragma unroll
            for (int ntp = 0; ntp < 4; ntp++) {
                uint32_t r4[4];
                ldsm_x4(r4, bbase + b_off + (uint32_t)(ntp * 16 * ROW_B) + koff);
                bfr[2 * ntp][0] = r4[0]; bfr[2 * ntp][1] = r4[1];
                bfr[2 * ntp + 1][0] = r4[2]; bfr[2 * ntp + 1][1] = r4[3];
            }
            #pragma unroll
            for (int mt = 0; mt < 4; mt++)
                #pragma unroll
                for (int nt = 0; nt < 8; nt++)
                    mma16816(acc[mt][nt], afr[mt], bfr[nt]);
        }
    }

    const int rl = lane >> 2, cl = 2 * (lane & 3);
    #pragma unroll
    for (int mt = 0; mt < 4; mt++) {
        const long r = row0 + wm * 64 + mt * 16 + rl;
        #pragma unroll
        for (int nt = 0; nt < 8; nt++) {
            const int c = wn * 64 + nt * 8 + cl;
            const long cg = (long)bx * BN + c;
            const float b0 = sBias[c], b1 = sBias[c + 1];
            if constexpr (sizeof(OutT) == 2) {
                __half2* p0 = (__half2*)((__half*)out + r * ldo + cg);
                __half2* p1 = (__half2*)((__half*)out + (r + 8) * ldo + cg);
                *p0 = __float22half2_rn(make_float2(acc[mt][nt][0] + b0, acc[mt][nt][1] + b1));
                *p1 = __float22half2_rn(make_float2(acc[mt][nt][2] + b0, acc[mt][nt][3] + b1));
            } else {
                float* o = (float*)out;
                *(float2*)&o[r * ldo + cg] =
                    make_float2(acc[mt][nt][0] + b0, acc[mt][nt][1] + b1);
                *(float2*)&o[(r + 8) * ldo + cg] =
                    make_float2(acc[mt][nt][2] + b0, acc[mt][nt][3] + b1);
            }
        }
    }
}

// ---------------------------------------------------------------------------
// Attention v6 — tensor-core MMA. Block = batch (256 thr), warp = head.
// Per warp: scores = Q(14x64)·K^T via 8 HMMA, softmax in registers (2 shfls
// per row), P reuses the C->A fragment layout identity, out = P·V via 8 HMMA.
// Q/K/V staged per head into 144B-stride smem (ldmatrix conflict-free),
// rows 14/15 zeroed; cols 14/15 masked to -1e30 pre-softmax.
// ---------------------------------------------------------------------------
#define AH_STRIDE 72                       // halves per row (144 B)
#define AH_BUF    (16 * AH_STRIDE)         // 1152 halves per 16-row buffer
#define ATTN_SM2  (8 * 3 * AH_BUF * 2 + 16 * 17 * 4)   // 55296 + 1088 = 56384 B

__global__ __launch_bounds__(256, 3)
void attn_kernel(const float* __restrict__ dist,
                 const float* __restrict__ scaleP,
                 const float* __restrict__ powerP)
{
    extern __shared__ char asmem[];
    __half* sQKV  = (__half*)asmem;                       // [8 heads][3][16][72]
    float*  sPrior = (float*)(asmem + 8 * 3 * AH_BUF * 2);// [16][17]

    const int tid = threadIdx.x, lane = tid & 31, h = tid >> 5;
    const int b = blockIdx.x;

    // Prior (scale/(1+d^p) * 1/sqrt(64)), zero outside 14x14
    {
        int n = tid >> 4, m = tid & 15;
        float pv = 0.f;
        if (n < SEQ && m < SEQ) {
            float d  = dist[n * SEQ + m];
            float p  = powerP[0];
            float sc = scaleP[0];
            float dp = (d > 0.f) ? expf(p * logf(d)) : 0.f;
            pv = sc / (1.f + dp) * 0.125f;
        }
        sPrior[n * 17 + m] = pv;
    }

    // Stage QKV per head: 2688 16B chunks + zero rows 14/15
    {
        const __half* src = g_QKVh + (size_t)b * 21504;
        for (int i = tid; i < 2688; i += 256) {
            int c = i & 7, t = i >> 3;          // t = (hh*3+rg)*14 + n
            int n = t % 14, hr = t / 14;
            int rg = hr % 3, hh = hr / 3;
            uint4 v = *(const uint4*)(src + n * 1536 + rg * 512 + hh * 64 + c * 8);
            *(uint4*)(sQKV + hr * AH_BUF + n * AH_STRIDE + c * 8) = v;
        }
        for (int i = tid; i < 384; i += 256) {  // 24 buffers x 2 rows x 8 chunks
            int c = i & 7, t = i >> 3;
            int rr = t & 1, hr = t >> 1;
            *(uint4*)(sQKV + hr * AH_BUF + (14 + rr) * AH_STRIDE + c * 8) =
                make_uint4(0, 0, 0, 0);
        }
    }
    __syncthreads();

    const uint32_t qb = smem_u32(sQKV + (h * 3 + 0) * AH_BUF);
    const uint32_t kb = smem_u32(sQKV + (h * 3 + 1) * AH_BUF);
    const uint32_t vb = smem_u32(sQKV + (h * 3 + 2) * AH_BUF);

    const int sub = lane >> 3, l7 = lane & 7;
    // A-operand pattern: lanes 0-7 rows0-7 klo | 8-15 rows8-15 klo | 16-23 rows0-7 khi | 24-31 rows8-15 khi
    const uint32_t aoff = (uint32_t)(((sub & 1) * 8 + l7) * 144 + (sub >> 1) * 16);
    // B-operand pattern: lanes 0-7 n0-7 klo | 8-15 n0-7 khi | 16-23 n8-15 klo | 24-31 n8-15 khi
    const uint32_t boff = (uint32_t)(((sub >> 1) * 8 + l7) * 144 + (sub & 1) * 16);

    // Scores: S0 = cols 0-7, S1 = cols 8-15 (rows r, r+8 per lane)
    float S0[4] = {0.f, 0.f, 0.f, 0.f}, S1[4] = {0.f, 0.f, 0.f, 0.f};
    #pragma unroll
    for (int ks = 0; ks < 4; ks++) {
        uint32_t af[4], bf4[4];
        ldsm_x4(af, qb + aoff + (uint32_t)(ks * 32));
        ldsm_x4(bf4, kb + boff + (uint32_t)(ks * 32));
        uint32_t b0[2] = {bf4[0], bf4[1]};
        uint32_t b1[2] = {bf4[2], bf4[3]};
        mma16816(S0, af, b0);
        mma16816(S1, af, b1);
    }

    // Apply prior, mask cols 14/15, softmax per row
    const int r = lane >> 2, c2 = 2 * (lane & 3);
    {
        const float* pr0 = sPrior + r * 17;
        const float* pr8 = sPrior + (r + 8) * 17;
        S0[0] *= pr0[c2];     S0[1] *= pr0[c2 + 1];
        S0[2] *= pr8[c2];     S0[3] *= pr8[c2 + 1];
        S1[0] *= pr0[8 + c2]; S1[1] *= pr0[9 + c2];
        S1[2] *= pr8[8 + c2]; S1[3] *= pr8[9 + c2];
    }
    if ((lane & 3) == 3) { S1[0] = S1[1] = -1e30f; S1[2] = S1[3] = -1e30f; }

    // row r: S0[0],S0[1],S1[0],S1[1]; row r+8: S0[2],S0[3],S1[2],S1[3]
    float mA = fmaxf(fmaxf(S0[0], S0[1]), fmaxf(S1[0], S1[1]));
    float mB = fmaxf(fmaxf(S0[2], S0[3]), fmaxf(S1[2], S1[3]));
    mA = fmaxf(mA, __shfl_xor_sync(0xffffffffu, mA, 1));
    mA = fmaxf(mA, __shfl_xor_sync(0xffffffffu, mA, 2));
    mB = fmaxf(mB, __shfl_xor_sync(0xffffffffu, mB, 1));
    mB = fmaxf(mB, __shfl_xor_sync(0xffffffffu, mB, 2));

    S0[0] = __expf(S0[0] - mA); S0[1] = __expf(S0[1] - mA);
    S1[0] = __expf(S1[0] - mA); S1[1] = __expf(S1[1] - mA);
    S0[2] = __expf(S0[2] - mB); S0[3] = __expf(S0[3] - mB);
    S1[2] = __expf(S1[2] - mB); S1[3] = __expf(S1[3] - mB);

    float sA = S0[0] + S0[1] + S1[0] + S1[1];
    float sB = S0[2] + S0[3] + S1[2] + S1[3];
    sA += __shfl_xor_sync(0xffffffffu, sA, 1);
    sA += __shfl_xor_sync(0xffffffffu, sA, 2);
    sB += __shfl_xor_sync(0xffffffffu, sB, 1);
    sB += __shfl_xor_sync(0xffffffffu, sB, 2);
    const float iA = 1.f / sA, iB = 1.f / sB;

    // Pack P to fp16 A-fragment (C layout == A layout)
    uint32_t pa[4];
    {
        __half2 h0 = __float22half2_rn(make_float2(S0[0] * iA, S0[1] * iA));
        __half2 h1 = __float22half2_rn(make_float2(S0[2] * iB, S0[3] * iB));
        __half2 h2 = __float22half2_rn(make_float2(S1[0] * iA, S1[1] * iA));
        __half2 h3 = __float22half2_rn(make_float2(S1[2] * iB, S1[3] * iB));
        pa[0] = *(uint32_t*)&h0; pa[1] = *(uint32_t*)&h1;
        pa[2] = *(uint32_t*)&h2; pa[3] = *(uint32_t*)&h3;
    }

    // Out = P @ V; V B-fragments via ldmatrix.trans (V is [m][d] row-major)
    __half* ob = g_attnh + (size_t)b * (SEQ * 512) + h * 64;
    #pragma unroll
    for (int dp2 = 0; dp2 < 4; dp2++) {          // two 8-wide d-tiles per iter
        uint32_t vf[4];
        ldsm_x4_t(vf, vb + aoff + (uint32_t)(dp2 * 32));
        uint32_t bb0[2] = {vf[0], vf[1]};
        uint32_t bb1[2] = {vf[2], vf[3]};
        float o0[4] = {0.f, 0.f, 0.f, 0.f}, o1[4] = {0.f, 0.f, 0.f, 0.f};
        mma16816(o0, pa, bb0);
        mma16816(o1, pa, bb1);

        const int d0 = dp2 * 16 + c2;            // cols of first d-tile
        const int d1 = dp2 * 16 + 8 + c2;        // cols of second d-tile
        __half2 w0 = __float22half2_rn(make_float2(o0[0], o0[1]));
        __half2 w1 = __float22half2_rn(make_float2(o1[0], o1[1]));
        *(__half2*)(ob + r * 512 + d0) = w0;     // r in 0..7 < 14 always
        *(__half2*)(ob + r * 512 + d1) = w1;
        if (r < 6) {                             // rows 8..13
            __half2 w2 = __float22half2_rn(make_float2(o0[2], o0[3]));
            __half2 w3 = __float22half2_rn(make_float2(o1[2], o1[3]));
            *(__half2*)(ob + (r + 8) * 512 + d0) = w2;
            *(__half2*)(ob + (r + 8) * 512 + d1) = w3;
        }
    }
}

// ---------------------------------------------------------------------------
// Conversions
// ---------------------------------------------------------------------------
__global__ void conv_x_kernel(const float* __restrict__ x, __half* __restrict__ o, long n4) {
    long i = (long)blockIdx.x * blockDim.x + threadIdx.x;
    const long stride = (long)gridDim.x * blockDim.x;
    const float4* xi = (const float4*)x;
    for (; i < n4; i += stride) {
        float4 v = xi[i];
        __half2 lo = __float22half2_rn(make_float2(v.x, v.y));
        __half2 hi = __float22half2_rn(make_float2(v.z, v.w));
        *(uint2*)(o + i * 4) = make_uint2(*(uint32_t*)&lo, *(uint32_t*)&hi);
    }
}

__global__ void conv_w_kernel(const float* __restrict__ Wq, const float* __restrict__ Wk,
                              const float* __restrict__ Wv, const float* __restrict__ Wo,
                              const float* __restrict__ bq, const float* __restrict__ bk,
                              const float* __restrict__ bv, const float* __restrict__ bo,
                              __half* __restrict__ Wc, float* __restrict__ bias) {
    int i = blockIdx.x * 256 + threadIdx.x;
    if (i < 2048 * 512) {
        int r = i >> 9, c = i & 511;
        const float* src = (r < 512) ? Wq : (r < 1024) ? Wk : (r < 1536) ? Wv : Wo;
        Wc[i] = __float2half_rn(src[(r & 511) * 512 + c]);
    }
    if (i < 2048) {
        const float* bs = (i < 512) ? bq : (i < 1024) ? bk : (i < 1536) ? bv : bo;
        bias[i] = bs[i & 511];
    }
}

// ---------------------------------------------------------------------------
// Launch
// ---------------------------------------------------------------------------
extern "C" void kernel_launch(void* const* d_in, const int* in_sizes, int n_in,
                              void* d_out, int out_size)
{
    const float* x     = (const float*)d_in[0];
    const float* Wq    = (const float*)d_in[1];
    const float* bq    = (const float*)d_in[2];
    const float* Wk    = (const float*)d_in[3];
    const float* bk    = (const float*)d_in[4];
    const float* Wv    = (const float*)d_in[5];
    const float* bv    = (const float*)d_in[6];
    const float* Wo    = (const float*)d_in[7];
    const float* bo    = (const float*)d_in[8];
    const float* scale = (const float*)d_in[9];
    const float* power = (const float*)d_in[10];
    const float* dist  = (const float*)d_in[11];
    float* out = (float*)d_out;

    __half *Xh = nullptr, *qkvh = nullptr, *attnh = nullptr, *Wh = nullptr;
    float *bias = nullptr;
    cudaGetSymbolAddress((void**)&Xh,    g_Xh);
    cudaGetSymbolAddress((void**)&qkvh,  g_QKVh);
    cudaGetSymbolAddress((void**)&attnh, g_attnh);
    cudaGetSymbolAddress((void**)&Wh,    g_Wh);
    cudaGetSymbolAddress((void**)&bias,  g_bias);

    cudaFuncSetAttribute(gemm_fp16<__half>, cudaFuncAttributeMaxDynamicSharedMemorySize, SM_TOTAL);
    cudaFuncSetAttribute(gemm_fp16<float>,  cudaFuncAttributeMaxDynamicSharedMemorySize, SM_TOTAL);
    cudaFuncSetAttribute(attn_kernel, cudaFuncAttributeMaxDynamicSharedMemorySize, ATTN_SM2);

    conv_x_kernel<<<4096, 256>>>(x, Xh, (long)MROWS * D_MODEL / 4);
    conv_w_kernel<<<4096, 256>>>(Wq, Wk, Wv, Wo, bq, bk, bv, bo, Wh, bias);

    // QKV projection -> g_QKVh [M x 1536] (half)
    gemm_fp16<__half><<<dim3(12, MROWS / BM), GTHREADS, SM_TOTAL>>>(Xh, Wh, bias, qkvh, 1536, 0);

    // Attention per batch item -> g_attnh (half)
    attn_kernel<<<BATCH, 256, ATTN_SM2>>>(dist, scale, power);

    // Output projection -> d_out [M x 512] (f32)
    gemm_fp16<float><<<dim3(4, MROWS / BM), GTHREADS, SM_TOTAL>>>(attnh, Wh, bias, out, 512, 1536);
}

// round 10
// speedup vs baseline: 1.1857x; 1.0164x over previous
#include <cuda_runtime.h>
#include <cuda_fp16.h>
#include <cstdint>

// ---------------------------------------------------------------------------
// Problem constants
// ---------------------------------------------------------------------------
#define D_MODEL 512
#define NHEAD   8
#define DK      64
#define BATCH   8192
#define SEQ     14
#define MROWS   (BATCH*SEQ)   // 114688

// Scratch (static device globals)
__device__ __half g_Xh  [(size_t)MROWS * D_MODEL];  // X in fp16
__device__ __half g_QKVh[(size_t)MROWS * 1536];     // Q|K|V fused, fp16
__device__ __half g_attnh[(size_t)MROWS * D_MODEL]; // attention out, fp16
__device__ __half g_Wh  [2048 * 512];               // Wq;Wk;Wv;Wo fp16 (row-major over k)
__device__ float  g_bias[2048];                     // bq;bk;bv;bo

// ---------------------------------------------------------------------------
// Helpers
// ---------------------------------------------------------------------------
__device__ __forceinline__ uint32_t smem_u32(const void* p) {
    uint32_t a;
    asm("{ .reg .u64 t; cvta.to.shared.u64 t, %1; cvt.u32.u64 %0, t; }" : "=r"(a) : "l"(p));
    return a;
}
__device__ __forceinline__ void cp16(uint32_t dst, const void* src) {
    asm volatile("cp.async.cg.shared.global [%0], [%1], 16;\n" :: "r"(dst), "l"(src));
}
__device__ __forceinline__ void cp_commit() { asm volatile("cp.async.commit_group;\n" ::: "memory"); }
template <int N> __device__ __forceinline__ void cp_wait() {
    asm volatile("cp.async.wait_group %0;\n" :: "n"(N) : "memory");
}
__device__ __forceinline__ void ldsm_x4(uint32_t r[4], uint32_t addr) {
    asm volatile("ldmatrix.sync.aligned.m8n8.x4.shared.b16 {%0,%1,%2,%3}, [%4];"
                 : "=r"(r[0]), "=r"(r[1]), "=r"(r[2]), "=r"(r[3]) : "r"(addr));
}
__device__ __forceinline__ void ldsm_x4_t(uint32_t r[4], uint32_t addr) {
    asm volatile("ldmatrix.sync.aligned.m8n8.x4.trans.shared.b16 {%0,%1,%2,%3}, [%4];"
                 : "=r"(r[0]), "=r"(r[1]), "=r"(r[2]), "=r"(r[3]) : "r"(addr));
}
__device__ __forceinline__ void mma16816(float c[4], const uint32_t a[4], const uint32_t b[2]) {
    asm volatile(
        "mma.sync.aligned.m16n8k16.row.col.f32.f16.f16.f32 "
        "{%0,%1,%2,%3}, {%4,%5,%6,%7}, {%8,%9}, {%0,%1,%2,%3};\n"
        : "+f"(c[0]), "+f"(c[1]), "+f"(c[2]), "+f"(c[3])
        : "r"(a[0]), "r"(a[1]), "r"(a[2]), "r"(a[3]), "r"(b[0]), "r"(b[1]));
}

// ---------------------------------------------------------------------------
// fp16 multistage GEMM: CTA 128x128, BK=64 (4 k16 slabs/stage), 3-stage
// cp.async pipeline (half the barriers of BK=32/4-stage), 4 warps (64x64
// warp tile), ldmatrix fragments. Row stride 144B: 9i mod 8 distinct ->
// conflict-free ldmatrix.
// ---------------------------------------------------------------------------
#define BM 128
#define BN 128
#define BK 64
#define NSTAGE 3
#define NK (D_MODEL / BK)               // 8
#define ROW_B 144                       // 128B data + 16B pad
#define A_ST  (BM * ROW_B)              // 18432
#define B_ST  (BN * ROW_B)              // 18432
#define STAGE (A_ST + B_ST)             // 36864
#define SM_BIAS (NSTAGE * STAGE)        // 110592
#define SM_TOTAL (SM_BIAS + BN * 4)     // 111104
#define GTHREADS 128

__device__ __forceinline__ void issue_stage(uint32_t sb, int buf, int ks,
                                            const __half* __restrict__ Abase,
                                            const __half* __restrict__ Wbase,
                                            int tid) {
    const uint32_t adst = sb + buf * STAGE;
    const uint32_t bdst = adst + A_ST;
    const int kb = ks * BK;
    #pragma unroll
    for (int t = 0; t < 8; t++) {        // A: 1024 x 16B chunks
        int c = tid + t * GTHREADS;
        int r = c >> 3, kc = c & 7;      // row 0..127, 16B chunk 0..7
        cp16(adst + (uint32_t)(r * ROW_B + kc * 16), Abase + (long)r * D_MODEL + kb + kc * 8);
    }
    #pragma unroll
    for (int t = 0; t < 8; t++) {        // B: 1024 x 16B chunks
        int c = tid + t * GTHREADS;
        int r = c >> 3, kc = c & 7;
        cp16(bdst + (uint32_t)(r * ROW_B + kc * 16), Wbase + (long)r * D_MODEL + kb + kc * 8);
    }
}

template <typename OutT>
__global__ __launch_bounds__(GTHREADS, 2)
void gemm_fp16(const __half* __restrict__ A, const __half* __restrict__ W,
               const float* __restrict__ bias, OutT* __restrict__ out,
               int ldo, int wbase)
{
    extern __shared__ char smem[];
    const uint32_t sb = smem_u32(smem);
    float* sBias = (float*)(smem + SM_BIAS);

    const int tid = threadIdx.x;
    const int wid = tid >> 5, lane = tid & 31;
    const int wm = wid >> 1, wn = wid & 1;       // warp tile: rows wm*64, cols wn*64
    const int bx = blockIdx.x, by = blockIdx.y;
    const long row0  = (long)by * BM;
    const int  wrow0 = wbase + bx * BN;

    if (tid < BN) sBias[tid] = bias[wrow0 + tid];

    const __half* Abase = A + row0 * D_MODEL;
    const __half* Wbase = W + (long)wrow0 * D_MODEL;

    float acc[4][8][4];
    #pragma unroll
    for (int i = 0; i < 4; i++)
        #pragma unroll
        for (int j = 0; j < 8; j++)
            #pragma unroll
            for (int k = 0; k < 4; k++) acc[i][j][k] = 0.f;

    const int sub = lane >> 3, l7 = lane & 7;
    const uint32_t a_off = (uint32_t)((wm * 64 + (sub & 1) * 8 + l7) * ROW_B + (sub >> 1) * 16);
    const uint32_t b_off = (uint32_t)((wn * 64 + (sub >> 1) * 8 + l7) * ROW_B + (sub & 1) * 16);

    #pragma unroll
    for (int s = 0; s < NSTAGE - 1; s++) { issue_stage(sb, s, s, Abase, Wbase, tid); cp_commit(); }

    for (int ks = 0; ks < NK; ks++) {
        const int buf = ks % NSTAGE;
        cp_wait<NSTAGE - 2>();
        __syncthreads();

        const int pf = ks + NSTAGE - 1;
        if (pf < NK) issue_stage(sb, pf % NSTAGE, pf, Abase, Wbase, tid);
        cp_commit();

        const uint32_t abase = sb + buf * STAGE;
        const uint32_t bbase = abase + A_ST;
        #pragma unroll
        for (int slab = 0; slab < 4; slab++) {      // four k16 slabs per stage
            const uint32_t koff = (uint32_t)(slab * 32);
            uint32_t afr[4][4], bfr[8][2];
            #pragma unroll
            for (int mt = 0; mt < 4; mt++)
                ldsm_x4(afr[mt], abase + a_off + (uint32_t)(mt * 16 * ROW_B) + koff);
            #pragma unroll
            for (int ntp = 0; ntp < 4; ntp++) {
                uint32_t r4[4];
                ldsm_x4(r4, bbase + b_off + (uint32_t)(ntp * 16 * ROW_B) + koff);
                bfr[2 * ntp][0] = r4[0]; bfr[2 * ntp][1] = r4[1];
                bfr[2 * ntp + 1][0] = r4[2]; bfr[2 * ntp + 1][1] = r4[3];
            }
            #pragma unroll
            for (int mt = 0; mt < 4; mt++)
                #pragma unroll
                for (int nt = 0; nt < 8; nt++)
                    mma16816(acc[mt][nt], afr[mt], bfr[nt]);
        }
    }

    const int rl = lane >> 2, cl = 2 * (lane & 3);
    #pragma unroll
    for (int mt = 0; mt < 4; mt++) {
        const long r = row0 + wm * 64 + mt * 16 + rl;
        #pragma unroll
        for (int nt = 0; nt < 8; nt++) {
            const int c = wn * 64 + nt * 8 + cl;
            const long cg = (long)bx * BN + c;
            const float b0 = sBias[c], b1 = sBias[c + 1];
            if constexpr (sizeof(OutT) == 2) {
                __half2* p0 = (__half2*)((__half*)out + r * ldo + cg);
                __half2* p1 = (__half2*)((__half*)out + (r + 8) * ldo + cg);
                *p0 = __float22half2_rn(make_float2(acc[mt][nt][0] + b0, acc[mt][nt][1] + b1));
                *p1 = __float22half2_rn(make_float2(acc[mt][nt][2] + b0, acc[mt][nt][3] + b1));
            } else {
                float* o = (float*)out;
                *(float2*)&o[r * ldo + cg] =
                    make_float2(acc[mt][nt][0] + b0, acc[mt][nt][1] + b1);
                *(float2*)&o[(r + 8) * ldo + cg] =
                    make_float2(acc[mt][nt][2] + b0, acc[mt][nt][3] + b1);
            }
        }
    }
}

// ---------------------------------------------------------------------------
// Attention (tensor-core, unchanged logic from R7; occupancy hint -> 4 CTA/SM).
// Block = batch (256 thr), warp = head. 8 HMMA scores + 8 HMMA out per warp;
// softmax in registers (2 shfls/row); P converts in-register (C layout == A
// layout). Rows 14/15 zeroed in smem; cols 14/15 masked pre-softmax.
// ---------------------------------------------------------------------------
#define AH_STRIDE 72                       // halves per row (144 B)
#define AH_BUF    (16 * AH_STRIDE)         // 1152 halves per 16-row buffer
#define ATTN_SM2  (8 * 3 * AH_BUF * 2 + 16 * 17 * 4)   // 55296 + 1088 = 56384 B

__global__ __launch_bounds__(256, 4)
void attn_kernel(const float* __restrict__ dist,
                 const float* __restrict__ scaleP,
                 const float* __restrict__ powerP)
{
    extern __shared__ char asmem[];
    __half* sQKV  = (__half*)asmem;                       // [8 heads][3][16][72]
    float*  sPrior = (float*)(asmem + 8 * 3 * AH_BUF * 2);// [16][17]

    const int tid = threadIdx.x, lane = tid & 31, h = tid >> 5;
    const int b = blockIdx.x;

    // Prior (scale/(1+d^p) * 1/sqrt(64)), zero outside 14x14
    {
        int n = tid >> 4, m = tid & 15;
        float pv = 0.f;
        if (n < SEQ && m < SEQ) {
            float d  = dist[n * SEQ + m];
            float p  = powerP[0];
            float sc = scaleP[0];
            float dp = (d > 0.f) ? expf(p * logf(d)) : 0.f;
            pv = sc / (1.f + dp) * 0.125f;
        }
        sPrior[n * 17 + m] = pv;
    }

    // Stage QKV per head: 2688 16B chunks + zero rows 14/15
    {
        const __half* src = g_QKVh + (size_t)b * 21504;
        for (int i = tid; i < 2688; i += 256) {
            int c = i & 7, t = i >> 3;          // t = (hh*3+rg)*14 + n
            int n = t % 14, hr = t / 14;
            int rg = hr % 3, hh = hr / 3;
            uint4 v = *(const uint4*)(src + n * 1536 + rg * 512 + hh * 64 + c * 8);
            *(uint4*)(sQKV + hr * AH_BUF + n * AH_STRIDE + c * 8) = v;
        }
        for (int i = tid; i < 384; i += 256) {  // 24 buffers x 2 rows x 8 chunks
            int c = i & 7, t = i >> 3;
            int rr = t & 1, hr = t >> 1;
            *(uint4*)(sQKV + hr * AH_BUF + (14 + rr) * AH_STRIDE + c * 8) =
                make_uint4(0, 0, 0, 0);
        }
    }
    __syncthreads();

    const uint32_t qb = smem_u32(sQKV + (h * 3 + 0) * AH_BUF);
    const uint32_t kb = smem_u32(sQKV + (h * 3 + 1) * AH_BUF);
    const uint32_t vb = smem_u32(sQKV + (h * 3 + 2) * AH_BUF);

    const int sub = lane >> 3, l7 = lane & 7;
    const uint32_t aoff = (uint32_t)(((sub & 1) * 8 + l7) * 144 + (sub >> 1) * 16);
    const uint32_t boff = (uint32_t)(((sub >> 1) * 8 + l7) * 144 + (sub & 1) * 16);

    // Scores: S0 = cols 0-7, S1 = cols 8-15 (rows r, r+8 per lane)
    float S0[4] = {0.f, 0.f, 0.f, 0.f}, S1[4] = {0.f, 0.f, 0.f, 0.f};
    #pragma unroll
    for (int ks = 0; ks < 4; ks++) {
        uint32_t af[4], bf4[4];
        ldsm_x4(af, qb + aoff + (uint32_t)(ks * 32));
        ldsm_x4(bf4, kb + boff + (uint32_t)(ks * 32));
        uint32_t b0[2] = {bf4[0], bf4[1]};
        uint32_t b1[2] = {bf4[2], bf4[3]};
        mma16816(S0, af, b0);
        mma16816(S1, af, b1);
    }

    // Apply prior, mask cols 14/15, softmax per row
    const int r = lane >> 2, c2 = 2 * (lane & 3);
    {
        const float* pr0 = sPrior + r * 17;
        const float* pr8 = sPrior + (r + 8) * 17;
        S0[0] *= pr0[c2];     S0[1] *= pr0[c2 + 1];
        S0[2] *= pr8[c2];     S0[3] *= pr8[c2 + 1];
        S1[0] *= pr0[8 + c2]; S1[1] *= pr0[9 + c2];
        S1[2] *= pr8[8 + c2]; S1[3] *= pr8[9 + c2];
    }
    if ((lane & 3) == 3) { S1[0] = S1[1] = -1e30f; S1[2] = S1[3] = -1e30f; }

    float mA = fmaxf(fmaxf(S0[0], S0[1]), fmaxf(S1[0], S1[1]));
    float mB = fmaxf(fmaxf(S0[2], S0[3]), fmaxf(S1[2], S1[3]));
    mA = fmaxf(mA, __shfl_xor_sync(0xffffffffu, mA, 1));
    mA = fmaxf(mA, __shfl_xor_sync(0xffffffffu, mA, 2));
    mB = fmaxf(mB, __shfl_xor_sync(0xffffffffu, mB, 1));
    mB = fmaxf(mB, __shfl_xor_sync(0xffffffffu, mB, 2));

    S0[0] = __expf(S0[0] - mA); S0[1] = __expf(S0[1] - mA);
    S1[0] = __expf(S1[0] - mA); S1[1] = __expf(S1[1] - mA);
    S0[2] = __expf(S0[2] - mB); S0[3] = __expf(S0[3] - mB);
    S1[2] = __expf(S1[2] - mB); S1[3] = __expf(S1[3] - mB);

    float sA = S0[0] + S0[1] + S1[0] + S1[1];
    float sB = S0[2] + S0[3] + S1[2] + S1[3];
    sA += __shfl_xor_sync(0xffffffffu, sA, 1);
    sA += __shfl_xor_sync(0xffffffffu, sA, 2);
    sB += __shfl_xor_sync(0xffffffffu, sB, 1);
    sB += __shfl_xor_sync(0xffffffffu, sB, 2);
    const float iA = 1.f / sA, iB = 1.f / sB;

    // Pack P to fp16 A-fragment (C layout == A layout)
    uint32_t pa[4];
    {
        __half2 h0 = __float22half2_rn(make_float2(S0[0] * iA, S0[1] * iA));
        __half2 h1 = __float22half2_rn(make_float2(S0[2] * iB, S0[3] * iB));
        __half2 h2 = __float22half2_rn(make_float2(S1[0] * iA, S1[1] * iA));
        __half2 h3 = __float22half2_rn(make_float2(S1[2] * iB, S1[3] * iB));
        pa[0] = *(uint32_t*)&h0; pa[1] = *(uint32_t*)&h1;
        pa[2] = *(uint32_t*)&h2; pa[3] = *(uint32_t*)&h3;
    }

    // Out = P @ V; V B-fragments via ldmatrix.trans (V is [m][d] row-major)
    __half* ob = g_attnh + (size_t)b * (SEQ * 512) + h * 64;
    #pragma unroll
    for (int dp2 = 0; dp2 < 4; dp2++) {          // two 8-wide d-tiles per iter
        uint32_t vf[4];
        ldsm_x4_t(vf, vb + aoff + (uint32_t)(dp2 * 32));
        uint32_t bb0[2] = {vf[0], vf[1]};
        uint32_t bb1[2] = {vf[2], vf[3]};
        float o0[4] = {0.f, 0.f, 0.f, 0.f}, o1[4] = {0.f, 0.f, 0.f, 0.f};
        mma16816(o0, pa, bb0);
        mma16816(o1, pa, bb1);

        const int d0 = dp2 * 16 + c2;
        const int d1 = dp2 * 16 + 8 + c2;
        __half2 w0 = __float22half2_rn(make_float2(o0[0], o0[1]));
        __half2 w1 = __float22half2_rn(make_float2(o1[0], o1[1]));
        *(__half2*)(ob + r * 512 + d0) = w0;
        *(__half2*)(ob + r * 512 + d1) = w1;
        if (r < 6) {
            __half2 w2 = __float22half2_rn(make_float2(o0[2], o0[3]));
            __half2 w3 = __float22half2_rn(make_float2(o1[2], o1[3]));
            *(__half2*)(ob + (r + 8) * 512 + d0) = w2;
            *(__half2*)(ob + (r + 8) * 512 + d1) = w3;
        }
    }
}

// ---------------------------------------------------------------------------
// Conversions
// ---------------------------------------------------------------------------
__global__ void conv_x_kernel(const float* __restrict__ x, __half* __restrict__ o, long n4) {
    long i = (long)blockIdx.x * blockDim.x + threadIdx.x;
    const long stride = (long)gridDim.x * blockDim.x;
    const float4* xi = (const float4*)x;
    for (; i < n4; i += stride) {
        float4 v = xi[i];
        __half2 lo = __float22half2_rn(make_float2(v.x, v.y));
        __half2 hi = __float22half2_rn(make_float2(v.z, v.w));
        *(uint2*)(o + i * 4) = make_uint2(*(uint32_t*)&lo, *(uint32_t*)&hi);
    }
}

__global__ void conv_w_kernel(const float* __restrict__ Wq, const float* __restrict__ Wk,
                              const float* __restrict__ Wv, const float* __restrict__ Wo,
                              const float* __restrict__ bq, const float* __restrict__ bk,
                              const float* __restrict__ bv, const float* __restrict__ bo,
                              __half* __restrict__ Wc, float* __restrict__ bias) {
    int i = blockIdx.x * 256 + threadIdx.x;
    if (i < 2048 * 512) {
        int r = i >> 9, c = i & 511;
        const float* src = (r < 512) ? Wq : (r < 1024) ? Wk : (r < 1536) ? Wv : Wo;
        Wc[i] = __float2half_rn(src[(r & 511) * 512 + c]);
    }
    if (i < 2048) {
        const float* bs = (i < 512) ? bq : (i < 1024) ? bk : (i < 1536) ? bv : bo;
        bias[i] = bs[i & 511];
    }
}

// ---------------------------------------------------------------------------
// Launch
// ---------------------------------------------------------------------------
extern "C" void kernel_launch(void* const* d_in, const int* in_sizes, int n_in,
                              void* d_out, int out_size)
{
    const float* x     = (const float*)d_in[0];
    const float* Wq    = (const float*)d_in[1];
    const float* bq    = (const float*)d_in[2];
    const float* Wk    = (const float*)d_in[3];
    const float* bk    = (const float*)d_in[4];
    const float* Wv    = (const float*)d_in[5];
    const float* bv    = (const float*)d_in[6];
    const float* Wo    = (const float*)d_in[7];
    const float* bo    = (const float*)d_in[8];
    const float* scale = (const float*)d_in[9];
    const float* power = (const float*)d_in[10];
    const float* dist  = (const float*)d_in[11];
    float* out = (float*)d_out;

    __half *Xh = nullptr, *qkvh = nullptr, *attnh = nullptr, *Wh = nullptr;
    float *bias = nullptr;
    cudaGetSymbolAddress((void**)&Xh,    g_Xh);
    cudaGetSymbolAddress((void**)&qkvh,  g_QKVh);
    cudaGetSymbolAddress((void**)&attnh, g_attnh);
    cudaGetSymbolAddress((void**)&Wh,    g_Wh);
    cudaGetSymbolAddress((void**)&bias,  g_bias);

    cudaFuncSetAttribute(gemm_fp16<__half>, cudaFuncAttributeMaxDynamicSharedMemorySize, SM_TOTAL);
    cudaFuncSetAttribute(gemm_fp16<float>,  cudaFuncAttributeMaxDynamicSharedMemorySize, SM_TOTAL);
    cudaFuncSetAttribute(attn_kernel, cudaFuncAttributeMaxDynamicSharedMemorySize, ATTN_SM2);

    conv_x_kernel<<<4096, 256>>>(x, Xh, (long)MROWS * D_MODEL / 4);
    conv_w_kernel<<<4096, 256>>>(Wq, Wk, Wv, Wo, bq, bk, bv, bo, Wh, bias);

    // QKV projection -> g_QKVh [M x 1536] (half)
    gemm_fp16<__half><<<dim3(12, MROWS / BM), GTHREADS, SM_TOTAL>>>(Xh, Wh, bias, qkvh, 1536, 0);

    // Attention per batch item -> g_attnh (half)
    attn_kernel<<<BATCH, 256, ATTN_SM2>>>(dist, scale, power);

    // Output projection -> d_out [M x 512] (f32)
    gemm_fp16<float><<<dim3(4, MROWS / BM), GTHREADS, SM_TOTAL>>>(attnh, Wh, bias, out, 512, 1536);
}

// round 11
// speedup vs baseline: 1.2686x; 1.0700x over previous
#include <cuda_runtime.h>
#include <cuda_fp16.h>
#include <cstdint>

// ---------------------------------------------------------------------------
// Problem constants
// ---------------------------------------------------------------------------
#define D_MODEL 512
#define NHEAD   8
#define DK      64
#define BATCH   8192
#define SEQ     14
#define MROWS   (BATCH*SEQ)   // 114688

// Scratch (static device globals)
__device__ __half g_Xh  [(size_t)MROWS * D_MODEL];  // X in fp16
__device__ __half g_QKVh[(size_t)MROWS * 1536];     // Q|K|V fused, fp16
__device__ __half g_attnh[(size_t)MROWS * D_MODEL]; // attention out, fp16
__device__ __half g_Wh  [2048 * 512];               // Wq;Wk;Wv;Wo fp16 (row-major over k)
__device__ float  g_bias[2048];                     // bq;bk;bv;bo

// ---------------------------------------------------------------------------
// Helpers
// ---------------------------------------------------------------------------
__device__ __forceinline__ uint32_t smem_u32(const void* p) {
    uint32_t a;
    asm("{ .reg .u64 t; cvta.to.shared.u64 t, %1; cvt.u32.u64 %0, t; }" : "=r"(a) : "l"(p));
    return a;
}
__device__ __forceinline__ void cp16(uint32_t dst, const void* src) {
    asm volatile("cp.async.cg.shared.global [%0], [%1], 16;\n" :: "r"(dst), "l"(src));
}
__device__ __forceinline__ void cp_commit() { asm volatile("cp.async.commit_group;\n" ::: "memory"); }
template <int N> __device__ __forceinline__ void cp_wait() {
    asm volatile("cp.async.wait_group %0;\n" :: "n"(N) : "memory");
}
__device__ __forceinline__ void ldsm_x4(uint32_t r[4], uint32_t addr) {
    asm volatile("ldmatrix.sync.aligned.m8n8.x4.shared.b16 {%0,%1,%2,%3}, [%4];"
                 : "=r"(r[0]), "=r"(r[1]), "=r"(r[2]), "=r"(r[3]) : "r"(addr));
}
__device__ __forceinline__ void ldsm_x4_t(uint32_t r[4], uint32_t addr) {
    asm volatile("ldmatrix.sync.aligned.m8n8.x4.trans.shared.b16 {%0,%1,%2,%3}, [%4];"
                 : "=r"(r[0]), "=r"(r[1]), "=r"(r[2]), "=r"(r[3]) : "r"(addr));
}
__device__ __forceinline__ void mma16816(float c[4], const uint32_t a[4], const uint32_t b[2]) {
    asm volatile(
        "mma.sync.aligned.m16n8k16.row.col.f32.f16.f16.f32 "
        "{%0,%1,%2,%3}, {%4,%5,%6,%7}, {%8,%9}, {%0,%1,%2,%3};\n"
        : "+f"(c[0]), "+f"(c[1]), "+f"(c[2]), "+f"(c[3])
        : "r"(a[0]), "r"(a[1]), "r"(a[2]), "r"(a[3]), "r"(b[0]), "r"(b[1]));
}

// ---------------------------------------------------------------------------
// fp16 multistage GEMM: CTA 128x128, BK=64 (4 k16 slabs/stage), 3-stage
// cp.async pipeline, 4 warps (64x64 warp tile), ldmatrix fragments with
// REGISTER DOUBLE-BUFFERING (slab k+1 LDSM overlaps slab k HMMA).
// Row stride 144B -> conflict-free ldmatrix.
// ---------------------------------------------------------------------------
#define BM 128
#define BN 128
#define BK 64
#define NSTAGE 3
#define NK (D_MODEL / BK)               // 8
#define ROW_B 144                       // 128B data + 16B pad
#define A_ST  (BM * ROW_B)              // 18432
#define B_ST  (BN * ROW_B)              // 18432
#define STAGE (A_ST + B_ST)             // 36864
#define SM_BIAS (NSTAGE * STAGE)        // 110592
#define SM_TOTAL (SM_BIAS + BN * 4)     // 111104
#define GTHREADS 128

__device__ __forceinline__ void issue_stage(uint32_t sb, int buf, int ks,
                                            const __half* __restrict__ Abase,
                                            const __half* __restrict__ Wbase,
                                            int tid) {
    const uint32_t adst = sb + buf * STAGE;
    const uint32_t bdst = adst + A_ST;
    const int kb = ks * BK;
    #pragma unroll
    for (int t = 0; t < 8; t++) {        // A: 1024 x 16B chunks
        int c = tid + t * GTHREADS;
        int r = c >> 3, kc = c & 7;
        cp16(adst + (uint32_t)(r * ROW_B + kc * 16), Abase + (long)r * D_MODEL + kb + kc * 8);
    }
    #pragma unroll
    for (int t = 0; t < 8; t++) {        // B: 1024 x 16B chunks
        int c = tid + t * GTHREADS;
        int r = c >> 3, kc = c & 7;
        cp16(bdst + (uint32_t)(r * ROW_B + kc * 16), Wbase + (long)r * D_MODEL + kb + kc * 8);
    }
}

__device__ __forceinline__ void load_frags(uint32_t abase, uint32_t bbase,
                                           uint32_t a_off, uint32_t b_off, int slab,
                                           uint32_t afr[4][4], uint32_t bfr[8][2]) {
    const uint32_t koff = (uint32_t)(slab * 32);
    #pragma unroll
    for (int mt = 0; mt < 4; mt++)
        ldsm_x4(afr[mt], abase + a_off + (uint32_t)(mt * 16 * ROW_B) + koff);
    #pragma unroll
    for (int ntp = 0; ntp < 4; ntp++) {
        uint32_t r4[4];
        ldsm_x4(r4, bbase + b_off + (uint32_t)(ntp * 16 * ROW_B) + koff);
        bfr[2 * ntp][0] = r4[0]; bfr[2 * ntp][1] = r4[1];
        bfr[2 * ntp + 1][0] = r4[2]; bfr[2 * ntp + 1][1] = r4[3];
    }
}

template <typename OutT>
__global__ __launch_bounds__(GTHREADS, 2)
void gemm_fp16(const __half* __restrict__ A, const __half* __restrict__ W,
               const float* __restrict__ bias, OutT* __restrict__ out,
               int ldo, int wbase)
{
    extern __shared__ char smem[];
    const uint32_t sb = smem_u32(smem);
    float* sBias = (float*)(smem + SM_BIAS);

    const int tid = threadIdx.x;
    const int wid = tid >> 5, lane = tid & 31;
    const int wm = wid >> 1, wn = wid & 1;       // warp tile: rows wm*64, cols wn*64
    const int bx = blockIdx.x, by = blockIdx.y;
    const long row0  = (long)by * BM;
    const int  wrow0 = wbase + bx * BN;

    if (tid < BN) sBias[tid] = bias[wrow0 + tid];

    const __half* Abase = A + row0 * D_MODEL;
    const __half* Wbase = W + (long)wrow0 * D_MODEL;

    float acc[4][8][4];
    #pragma unroll
    for (int i = 0; i < 4; i++)
        #pragma unroll
        for (int j = 0; j < 8; j++)
            #pragma unroll
            for (int k = 0; k < 4; k++) acc[i][j][k] = 0.f;

    const int sub = lane >> 3, l7 = lane & 7;
    const uint32_t a_off = (uint32_t)((wm * 64 + (sub & 1) * 8 + l7) * ROW_B + (sub >> 1) * 16);
    const uint32_t b_off = (uint32_t)((wn * 64 + (sub >> 1) * 8 + l7) * ROW_B + (sub & 1) * 16);

    #pragma unroll
    for (int s = 0; s < NSTAGE - 1; s++) { issue_stage(sb, s, s, Abase, Wbase, tid); cp_commit(); }

    uint32_t afr[2][4][4], bfr[2][8][2];

    for (int ks = 0; ks < NK; ks++) {
        const int buf = ks % NSTAGE;
        cp_wait<NSTAGE - 2>();
        __syncthreads();

        const int pf = ks + NSTAGE - 1;
        if (pf < NK) issue_stage(sb, pf % NSTAGE, pf, Abase, Wbase, tid);
        cp_commit();

        const uint32_t abase = sb + buf * STAGE;
        const uint32_t bbase = abase + A_ST;

        load_frags(abase, bbase, a_off, b_off, 0, afr[0], bfr[0]);
        #pragma unroll
        for (int slab = 0; slab < 4; slab++) {
            const int cur = slab & 1;
            if (slab < 3)
                load_frags(abase, bbase, a_off, b_off, slab + 1, afr[cur ^ 1], bfr[cur ^ 1]);
            #pragma unroll
            for (int mt = 0; mt < 4; mt++)
                #pragma unroll
                for (int nt = 0; nt < 8; nt++)
                    mma16816(acc[mt][nt], afr[cur][mt], bfr[cur][nt]);
        }
    }

    const int rl = lane >> 2, cl = 2 * (lane & 3);
    #pragma unroll
    for (int mt = 0; mt < 4; mt++) {
        const long r = row0 + wm * 64 + mt * 16 + rl;
        #pragma unroll
        for (int nt = 0; nt < 8; nt++) {
            const int c = wn * 64 + nt * 8 + cl;
            const long cg = (long)bx * BN + c;
            const float b0 = sBias[c], b1 = sBias[c + 1];
            if constexpr (sizeof(OutT) == 2) {
                __half2* p0 = (__half2*)((__half*)out + r * ldo + cg);
                __half2* p1 = (__half2*)((__half*)out + (r + 8) * ldo + cg);
                *p0 = __float22half2_rn(make_float2(acc[mt][nt][0] + b0, acc[mt][nt][1] + b1));
                *p1 = __float22half2_rn(make_float2(acc[mt][nt][2] + b0, acc[mt][nt][3] + b1));
            } else {
                float* o = (float*)out;
                *(float2*)&o[r * ldo + cg] =
                    make_float2(acc[mt][nt][0] + b0, acc[mt][nt][1] + b1);
                *(float2*)&o[(r + 8) * ldo + cg] =
                    make_float2(acc[mt][nt][2] + b0, acc[mt][nt][3] + b1);
            }
        }
    }
}

// ---------------------------------------------------------------------------
// Attention v7 — tensor-core MMA + cross-batch cp.async pipelining.
// 2 batches per CTA (grid = BATCH/2, 256 thr, warp = head). Both QKV tiles
// issued via cp.async up front; compute(b0) overlaps b1's in-flight loads.
// Per warp per batch: 8 HMMA scores + softmax in regs + 8 HMMA out.
// Rows 14/15 zeroed (STS before waits); cols 14/15 masked pre-softmax.
// ---------------------------------------------------------------------------
#define AH_STRIDE 72                       // halves per row (144 B)
#define AH_BUF    (16 * AH_STRIDE)         // 1152 halves per (head,rg) buffer
#define AB_BUF    (24 * AH_BUF)            // 27648 halves per batch (55296 B)
#define ATTN_SM3  (2 * AB_BUF * 2 + 16 * 17 * 4)   // 110592 + 1088 = 111680 B

__device__ __forceinline__ void attn_stage(uint32_t dstb, const __half* __restrict__ src, int tid) {
    for (int i = tid; i < 2688; i += 256) {
        int c = i & 7, t = i >> 3;          // t = (hh*3+rg)*14 + n
        int n = t % 14, hr = t / 14;
        int rg = hr % 3, hh = hr / 3;
        cp16(dstb + (uint32_t)((hr * AH_BUF + n * AH_STRIDE + c * 8) * 2),
             src + n * 1536 + rg * 512 + hh * 64 + c * 8);
    }
}

__device__ __forceinline__ void attn_compute(const __half* sQKV, const float* sPrior,
                                             __half* __restrict__ obase,
                                             int h, int lane) {
    const uint32_t qb = smem_u32(sQKV + (h * 3 + 0) * AH_BUF);
    const uint32_t kb = smem_u32(sQKV + (h * 3 + 1) * AH_BUF);
    const uint32_t vb = smem_u32(sQKV + (h * 3 + 2) * AH_BUF);

    const int sub = lane >> 3, l7 = lane & 7;
    const uint32_t aoff = (uint32_t)(((sub & 1) * 8 + l7) * 144 + (sub >> 1) * 16);
    const uint32_t boff = (uint32_t)(((sub >> 1) * 8 + l7) * 144 + (sub & 1) * 16);

    float S0[4] = {0.f, 0.f, 0.f, 0.f}, S1[4] = {0.f, 0.f, 0.f, 0.f};
    #pragma unroll
    for (int ks = 0; ks < 4; ks++) {
        uint32_t af[4], bf4[4];
        ldsm_x4(af, qb + aoff + (uint32_t)(ks * 32));
        ldsm_x4(bf4, kb + boff + (uint32_t)(ks * 32));
        uint32_t b0[2] = {bf4[0], bf4[1]};
        uint32_t b1[2] = {bf4[2], bf4[3]};
        mma16816(S0, af, b0);
        mma16816(S1, af, b1);
    }

    const int r = lane >> 2, c2 = 2 * (lane & 3);
    {
        const float* pr0 = sPrior + r * 17;
        const float* pr8 = sPrior + (r + 8) * 17;
        S0[0] *= pr0[c2];     S0[1] *= pr0[c2 + 1];
        S0[2] *= pr8[c2];     S0[3] *= pr8[c2 + 1];
        S1[0] *= pr0[8 + c2]; S1[1] *= pr0[9 + c2];
        S1[2] *= pr8[8 + c2]; S1[3] *= pr8[9 + c2];
    }
    if ((lane & 3) == 3) { S1[0] = S1[1] = -1e30f; S1[2] = S1[3] = -1e30f; }

    float mA = fmaxf(fmaxf(S0[0], S0[1]), fmaxf(S1[0], S1[1]));
    float mB = fmaxf(fmaxf(S0[2], S0[3]), fmaxf(S1[2], S1[3]));
    mA = fmaxf(mA, __shfl_xor_sync(0xffffffffu, mA, 1));
    mA = fmaxf(mA, __shfl_xor_sync(0xffffffffu, mA, 2));
    mB = fmaxf(mB, __shfl_xor_sync(0xffffffffu, mB, 1));
    mB = fmaxf(mB, __shfl_xor_sync(0xffffffffu, mB, 2));

    S0[0] = __expf(S0[0] - mA); S0[1] = __expf(S0[1] - mA);
    S1[0] = __expf(S1[0] - mA); S1[1] = __expf(S1[1] - mA);
    S0[2] = __expf(S0[2] - mB); S0[3] = __expf(S0[3] - mB);
    S1[2] = __expf(S1[2] - mB); S1[3] = __expf(S1[3] - mB);

    float sA = S0[0] + S0[1] + S1[0] + S1[1];
    float sB = S0[2] + S0[3] + S1[2] + S1[3];
    sA += __shfl_xor_sync(0xffffffffu, sA, 1);
    sA += __shfl_xor_sync(0xffffffffu, sA, 2);
    sB += __shfl_xor_sync(0xffffffffu, sB, 1);
    sB += __shfl_xor_sync(0xffffffffu, sB, 2);
    const float iA = 1.f / sA, iB = 1.f / sB;

    uint32_t pa[4];
    {
        __half2 h0 = __float22half2_rn(make_float2(S0[0] * iA, S0[1] * iA));
        __half2 h1 = __float22half2_rn(make_float2(S0[2] * iB, S0[3] * iB));
        __half2 h2 = __float22half2_rn(make_float2(S1[0] * iA, S1[1] * iA));
        __half2 h3 = __float22half2_rn(make_float2(S1[2] * iB, S1[3] * iB));
        pa[0] = *(uint32_t*)&h0; pa[1] = *(uint32_t*)&h1;
        pa[2] = *(uint32_t*)&h2; pa[3] = *(uint32_t*)&h3;
    }

    __half* ob = obase + h * 64;
    #pragma unroll
    for (int dp2 = 0; dp2 < 4; dp2++) {
        uint32_t vf[4];
        ldsm_x4_t(vf, vb + aoff + (uint32_t)(dp2 * 32));
        uint32_t bb0[2] = {vf[0], vf[1]};
        uint32_t bb1[2] = {vf[2], vf[3]};
        float o0[4] = {0.f, 0.f, 0.f, 0.f}, o1[4] = {0.f, 0.f, 0.f, 0.f};
        mma16816(o0, pa, bb0);
        mma16816(o1, pa, bb1);

        const int d0 = dp2 * 16 + c2;
        const int d1 = dp2 * 16 + 8 + c2;
        __half2 w0 = __float22half2_rn(make_float2(o0[0], o0[1]));
        __half2 w1 = __float22half2_rn(make_float2(o1[0], o1[1]));
        *(__half2*)(ob + r * 512 + d0) = w0;
        *(__half2*)(ob + r * 512 + d1) = w1;
        if (r < 6) {
            __half2 w2 = __float22half2_rn(make_float2(o0[2], o0[3]));
            __half2 w3 = __float22half2_rn(make_float2(o1[2], o1[3]));
            *(__half2*)(ob + (r + 8) * 512 + d0) = w2;
            *(__half2*)(ob + (r + 8) * 512 + d1) = w3;
        }
    }
}

__global__ __launch_bounds__(256, 2)
void attn_kernel(const float* __restrict__ dist,
                 const float* __restrict__ scaleP,
                 const float* __restrict__ powerP)
{
    extern __shared__ char asmem[];
    __half* sQKV0  = (__half*)asmem;                       // batch 0: [24][16][72]
    __half* sQKV1  = sQKV0 + AB_BUF;                       // batch 1
    float*  sPrior = (float*)(asmem + 2 * AB_BUF * 2);     // [16][17]

    const int tid = threadIdx.x, lane = tid & 31, h = tid >> 5;
    const long b0 = (long)blockIdx.x * 2;
    const long b1 = b0 + 1;

    // Issue both batches' staging via cp.async (overlap with everything below)
    const uint32_t sb0 = smem_u32(sQKV0);
    const uint32_t sb1 = smem_u32(sQKV1);
    attn_stage(sb0, g_QKVh + (size_t)b0 * 21504, tid);
    cp_commit();
    attn_stage(sb1, g_QKVh + (size_t)b1 * 21504, tid);
    cp_commit();

    // Zero rows 14/15 of all 48 buffers (STS, independent of cp.async)
    for (int i = tid; i < 768; i += 256) {
        int c = i & 7, t = i >> 3;          // 96 (buf,row) pairs x 8 chunks
        int rr = t & 1, hr2 = t >> 1;       // hr2: 0..47 over both batches
        __half* base = (hr2 < 24) ? sQKV0 : sQKV1;
        int hr = hr2 % 24;
        *(uint4*)(base + hr * AH_BUF + (14 + rr) * AH_STRIDE + c * 8) =
            make_uint4(0, 0, 0, 0);
    }

    // Prior (scale/(1+d^p) * 1/sqrt(64)), zero outside 14x14
    {
        int n = tid >> 4, m = tid & 15;
        float pv = 0.f;
        if (n < SEQ && m < SEQ) {
            float d  = dist[n * SEQ + m];
            float p  = powerP[0];
            float sc = scaleP[0];
            float dp = (d > 0.f) ? expf(p * logf(d)) : 0.f;
            pv = sc / (1.f + dp) * 0.125f;
        }
        sPrior[n * 17 + m] = pv;
    }

    // Batch 0: wait only its group (b1 still in flight -> overlap)
    cp_wait<1>();
    __syncthreads();
    attn_compute(sQKV0, sPrior, g_attnh + (size_t)b0 * (SEQ * 512), h, lane);

    // Batch 1
    cp_wait<0>();
    __syncthreads();
    attn_compute(sQKV1, sPrior, g_attnh + (size_t)b1 * (SEQ * 512), h, lane);
}

// ---------------------------------------------------------------------------
// Conversions
// ---------------------------------------------------------------------------
__global__ void conv_x_kernel(const float* __restrict__ x, __half* __restrict__ o, long n4) {
    long i = (long)blockIdx.x * blockDim.x + threadIdx.x;
    const long stride = (long)gridDim.x * blockDim.x;
    const float4* xi = (const float4*)x;
    for (; i < n4; i += stride) {
        float4 v = xi[i];
        __half2 lo = __float22half2_rn(make_float2(v.x, v.y));
        __half2 hi = __float22half2_rn(make_float2(v.z, v.w));
        *(uint2*)(o + i * 4) = make_uint2(*(uint32_t*)&lo, *(uint32_t*)&hi);
    }
}

__global__ void conv_w_kernel(const float* __restrict__ Wq, const float* __restrict__ Wk,
                              const float* __restrict__ Wv, const float* __restrict__ Wo,
                              const float* __restrict__ bq, const float* __restrict__ bk,
                              const float* __restrict__ bv, const float* __restrict__ bo,
                              __half* __restrict__ Wc, float* __restrict__ bias) {
    int i = blockIdx.x * 256 + threadIdx.x;
    if (i < 2048 * 512) {
        int r = i >> 9, c = i & 511;
        const float* src = (r < 512) ? Wq : (r < 1024) ? Wk : (r < 1536) ? Wv : Wo;
        Wc[i] = __float2half_rn(src[(r & 511) * 512 + c]);
    }
    if (i < 2048) {
        const float* bs = (i < 512) ? bq : (i < 1024) ? bk : (i < 1536) ? bv : bo;
        bias[i] = bs[i & 511];
    }
}

// ---------------------------------------------------------------------------
// Launch
// ---------------------------------------------------------------------------
extern "C" void kernel_launch(void* const* d_in, const int* in_sizes, int n_in,
                              void* d_out, int out_size)
{
    const float* x     = (const float*)d_in[0];
    const float* Wq    = (const float*)d_in[1];
    const float* bq    = (const float*)d_in[2];
    const float* Wk    = (const float*)d_in[3];
    const float* bk    = (const float*)d_in[4];
    const float* Wv    = (const float*)d_in[5];
    const float* bv    = (const float*)d_in[6];
    const float* Wo    = (const float*)d_in[7];
    const float* bo    = (const float*)d_in[8];
    const float* scale = (const float*)d_in[9];
    const float* power = (const float*)d_in[10];
    const float* dist  = (const float*)d_in[11];
    float* out = (float*)d_out;

    __half *Xh = nullptr, *qkvh = nullptr, *attnh = nullptr, *Wh = nullptr;
    float *bias = nullptr;
    cudaGetSymbolAddress((void**)&Xh,    g_Xh);
    cudaGetSymbolAddress((void**)&qkvh,  g_QKVh);
    cudaGetSymbolAddress((void**)&attnh, g_attnh);
    cudaGetSymbolAddress((void**)&Wh,    g_Wh);
    cudaGetSymbolAddress((void**)&bias,  g_bias);

    cudaFuncSetAttribute(gemm_fp16<__half>, cudaFuncAttributeMaxDynamicSharedMemorySize, SM_TOTAL);
    cudaFuncSetAttribute(gemm_fp16<float>,  cudaFuncAttributeMaxDynamicSharedMemorySize, SM_TOTAL);
    cudaFuncSetAttribute(attn_kernel, cudaFuncAttributeMaxDynamicSharedMemorySize, ATTN_SM3);

    conv_x_kernel<<<4096, 256>>>(x, Xh, (long)MROWS * D_MODEL / 4);
    conv_w_kernel<<<4096, 256>>>(Wq, Wk, Wv, Wo, bq, bk, bv, bo, Wh, bias);

    // QKV projection -> g_QKVh [M x 1536] (half)
    gemm_fp16<__half><<<dim3(12, MROWS / BM), GTHREADS, SM_TOTAL>>>(Xh, Wh, bias, qkvh, 1536, 0);

    // Attention: 2 batches per CTA, cp.async pipelined
    attn_kernel<<<BATCH / 2, 256, ATTN_SM3>>>(dist, scale, power);

    // Output projection -> d_out [M x 512] (f32)
    gemm_fp16<float><<<dim3(4, MROWS / BM), GTHREADS, SM_TOTAL>>>(attnh, Wh, bias, out, 512, 1536);
}